// round 15
// baseline (speedup 1.0000x reference)
#include <cuda_runtime.h>

#define BATCH 2
#define CH 384
#define CELLS 1024
#define TPC 64
#define SCALE 0.05103103630798287f   // 384^-0.5

// Scratch (device globals; allocation forbidden)
__device__ float g_tok  [(size_t)BATCH * CELLS * TPC * CH];   // raw x0, [blk][t][c]
__device__ float g_musig[(size_t)BATCH * CELLS * TPC * 2];    // per-token (beta=mu*rs, alpha=rs)
__device__ float g_stok [(size_t)BATCH * CELLS * CH];         // initial stokens
__device__ float g_stacc[4][(size_t)BATCH * CELLS * CH];      // per-iteration fold accumulators
__device__ float g_asum [4][BATCH * CELLS];

__global__ void knop() {}

__device__ __forceinline__ void cpa16p(unsigned dst, const float* src, int pbytes) {
    asm volatile("cp.async.ca.shared.global [%0], [%1], 16, %2;"
                 :: "r"(dst), "l"(src), "r"(pbytes));
}
__device__ __forceinline__ void cpa4p(unsigned dst, const float* src, int pbytes) {
    asm volatile("cp.async.ca.shared.global [%0], [%1], 4, %2;"
                 :: "r"(dst), "l"(src), "r"(pbytes));
}
__device__ __forceinline__ void cpa_commit() {
    asm volatile("cp.async.commit_group;" ::: "memory");
}

#define MBAR_INIT(mb, cnt) \
    asm volatile("mbarrier.init.shared.b64 [%0], %1;" :: "r"(mb), "r"(cnt) : "memory")
#define MBAR_EXPECT_TX(mb, tx) \
    asm volatile("mbarrier.arrive.expect_tx.shared.b64 _, [%0], %1;" :: "r"(mb), "r"(tx) : "memory")
#define MBAR_WAIT(mb, ph) do {                                              \
    asm volatile("{\n\t.reg .pred P;\n"                                     \
                 "WL%=:\n\t"                                                \
                 "mbarrier.try_wait.parity.acquire.cta.shared::cta.b64 P, [%0], %1, 0x989680;\n\t" \
                 "@P bra WD%=;\n\t"                                         \
                 "bra WL%=;\n"                                              \
                 "WD%=:\n\t}" :: "r"(mb), "r"(ph) : "memory");              \
} while (0)
#define BULK_G2S(dst, src, bytes, mb) \
    asm volatile("cp.async.bulk.shared::cluster.global.mbarrier::complete_tx::bytes [%0], [%1], %2, [%3];" \
                 :: "r"(dst), "l"(src), "r"(bytes), "r"(mb) : "memory")

// ---------------------------------------------------------------------------
// p1 (R7-exact, measured best 221us): dwconv3x3 + x + bias -> raw x0 tokens +
// LN stats + initial stokens. Block = 8x64 strip, 256 blocks x 512 threads.
// ---------------------------------------------------------------------------
__global__ __launch_bounds__(512, 2) void p1(const float* __restrict__ x,
                                             const float* __restrict__ dww,
                                             const float* __restrict__ dwb,
                                             const float* __restrict__ lng,
                                             const float* __restrict__ lnb) {
    extern __shared__ float sm[];
    float* tiles   = sm;                   // 2 * 5760
    float* wall    = sm + 11520;           // 3456
    float* ball    = wall + 3456;          // 384
    float* musig_s = ball + 384;           // 1024
    float* Scell   = musig_s + 1024;       // 8

    const int tid = threadIdx.x;
    const int blk = blockIdx.x;
    const int b = blk >> 7;
    const int rem = blk & 127;
    const int cellrow = rem >> 2;
    const int qc = rem & 3;
    const int h0 = cellrow * 8, w0 = qc * 64;

    const int px = tid;
    const int p0 = px >> 6, cc0 = px & 63;
    const int cell0 = cc0 >> 3, j0 = cc0 & 7;
    const int t0 = p0 * 8 + j0;
    const size_t cellbase = (size_t)(b * CELLS + cellrow * 32 + qc * 8);
    const size_t gcell0 = cellbase + cell0;
    float* tokrow = g_tok + (gcell0 * TPC + t0) * CH;

    for (int i = tid; i < 3456; i += 512) wall[i] = dww[i];
    if (tid < 384) ball[tid] = dwb[tid];

    const unsigned tA = (unsigned)__cvta_generic_to_shared(tiles);

    auto issue = [&](int j) {
        const int c0 = j * 8;
        const unsigned da = tA + (unsigned)((j & 1) * 5760 * 4);
        for (int i = tid; i < 1280; i += 512) {       // interior, 16B
            int r2 = i >> 7, rr = i & 127, ch = rr >> 4, c4 = rr & 15;
            int gh = h0 - 1 + r2;
            const float* src = x + (((size_t)(b * CH + c0 + ch)) << 16) + (gh << 8) + w0 + c4 * 4;
            cpa16p(da + (unsigned)((r2 * 576 + ch * 72 + 4 + c4 * 4) * 4), src,
                   ((unsigned)gh < 256u) ? 16 : 0);
        }
        for (int i = tid; i < 160; i += 512) {        // halo cols, 4B
            int r2 = i / 16, rr = i & 15, ch = rr >> 1, side = rr & 1;
            int gh = h0 - 1 + r2;
            int gw = side ? (w0 + 64) : (w0 - 1);
            const float* src = x + (((size_t)(b * CH + c0 + ch)) << 16) + (gh << 8) + gw;
            cpa4p(da + (unsigned)((r2 * 576 + ch * 72 + (side ? 68 : 3)) * 4), src,
                  ((unsigned)gh < 256u && (unsigned)gw < 256u) ? 4 : 0);
        }
        cpa_commit();
    };

    issue(0);
    issue(1);

    float s0 = 0.f, q0 = 0.f;

    for (int j = 0; j < 48; j++) {
        if (j < 47) asm volatile("cp.async.wait_group 1;" ::: "memory");
        else        asm volatile("cp.async.wait_group 0;" ::: "memory");
        __syncthreads();
        {
            const float* tile = tiles + (j & 1) * 5760;
            float v[8];
#pragma unroll
            for (int ch = 0; ch < 8; ch++) {
                const float* t0p = tile + p0 * 576 + ch * 72 + 3 + cc0;
                float a0 = t0p[0],    a1 = t0p[1],    a2 = t0p[2];
                float b0 = t0p[576],  b1 = t0p[577],  b2 = t0p[578];
                float d0 = t0p[1152], d1 = t0p[1153], d2 = t0p[1154];
                const float* w = wall + (j * 8 + ch) * 9;
                float vv = b1 + ball[j * 8 + ch]
                    + a0 * w[0] + a1 * w[1] + a2 * w[2]
                    + b0 * w[3] + b1 * w[4] + b2 * w[5]
                    + d0 * w[6] + d1 * w[7] + d2 * w[8];
                s0 += vv; q0 += vv * vv;
                v[ch] = vv;
            }
            *(float4*)(tokrow + j * 8)     = make_float4(v[0], v[1], v[2], v[3]);
            *(float4*)(tokrow + j * 8 + 4) = make_float4(v[4], v[5], v[6], v[7]);
        }
        __syncthreads();
        if (j < 46) issue(j + 2);
    }

    // LN stats
    {
        float mu = s0 * (1.f / CH);
        float rs = rsqrtf(q0 * (1.f / CH) - mu * mu + 1e-5f);
        *(float2*)(musig_s + px * 2) = make_float2(mu * rs, rs);
        *(float2*)(g_musig + (gcell0 * TPC + t0) * 2) = make_float2(mu * rs, rs);
    }
    __syncthreads();
    if (tid < 8) {
        float S = 0.f;
        for (int t = 0; t < TPC; t++) {
            int ppx = (t >> 3) * 64 + tid * 8 + (t & 7);
            S += musig_s[ppx * 2];
        }
        Scell[tid] = S;
    }
    __syncthreads();

    // Initial stokens (L2-hot re-read of own tokens)
    for (int u = tid; u < 8 * CH; u += 512) {
        int cell = u / CH, c = u - cell * CH;
        const float* tp = g_tok + (cellbase + cell) * TPC * CH + c;
        float acc = 0.f;
#pragma unroll 8
        for (int t = 0; t < TPC; t++) {
            int ppx = (t >> 3) * 64 + cell * 8 + (t & 7);
            acc += tp[t * CH] * musig_s[ppx * 2 + 1];
        }
        g_stok[(cellbase + cell) * CH + c] =
            lng[c] * (acc - Scell[cell]) * (1.f / 64.f) + lnb[c];
    }
}

// ---------------------------------------------------------------------------
// kz: zero all accumulator buffers
// ---------------------------------------------------------------------------
__global__ void kz() {
    int i = blockIdx.x * 256 + threadIdx.x;
    if (i < BATCH * CELLS * CH) {
#pragma unroll
        for (int r = 0; r < 4; r++) g_stacc[r][i] = 0.f;
        if (i < BATCH * CELLS) {
#pragma unroll
            for (int r = 0; r < 4; r++) g_asum[r][i] = 0.f;
        }
    }
}

// ---------------------------------------------------------------------------
// kb5: kb4 with 48-channel chunks (8-deep, 2 buffers, pitch 52) -> smem
// 48.3KB -> occupancy 4. Same bulk staging + mbarriers, same math.
// Z: [0..8]=W9, [9..17]=B9, [18..26]=T9, [27..35]=S9, [36..44]=recip(asum)
// ---------------------------------------------------------------------------
__global__ __launch_bounds__(384, 4) void kb5(const float* __restrict__ lng,
                                              const float* __restrict__ lnb,
                                              int it) {
    extern __shared__ float sm[];
    float* buf0 = sm;                 // 64*52 = 3328
    float* buf1 = sm + 3328;          // 3328
    float* st9T = sm + 6656;          // 4608
    float* L    = st9T + 4608;        // 768
    float* Z    = L + 768;            // 48
    // mbarriers at float index 12080 (byte 48320, 16B aligned)

    const int tid  = threadIdx.x;
    const int lane = tid & 31;
    const int blk  = blockIdx.x;
    const int b    = blk >> 10;
    const int cell = blk & 1023;
    const int bp = cell >> 5, bq = cell & 31;
    const float* tokbase = g_tok + (size_t)blk * TPC * CH;

    const unsigned smb = (unsigned)__cvta_generic_to_shared(sm);
    const unsigned b0a = smb;
    const unsigned b1a = smb + 3328u * 4u;
    const unsigned mb0 = smb + 12080u * 4u;
    const unsigned mb1 = mb0 + 8u;

    for (int i = tid; i < 768; i += 384) L[i] = 0.f;
    if (tid < 36) Z[tid] = 0.f;
    if (tid >= 36 && tid < 45) {
        int k = tid - 36;
        int mr = bp + k / 3 - 1, mc = bq + (k % 3) - 1;
        float r = 1.f;
        if (it > 0 && (unsigned)mr < 32u && (unsigned)mc < 32u)
            r = __fdividef(1.f, g_asum[it - 1][(b << 10) + mr * 32 + mc] + 1e-12f);
        Z[tid] = r;
    }
    if (tid == 0) { MBAR_INIT(mb0, 1); MBAR_INIT(mb1, 1); }
    __syncthreads();

    // stage chunk via 64 bulk row-copies (192B each)
    auto stage = [&](int chunk) {
        const unsigned mb = (chunk & 1) ? mb1 : mb0;
        const unsigned da = (chunk & 1) ? b1a : b0a;
        if (tid == 0) MBAR_EXPECT_TX(mb, 12288u);
        if (tid < 64)
            BULK_G2S(da + (unsigned)tid * 208u,
                     tokbase + tid * CH + chunk * 48, 192u, mb);
    };

    stage(0);
    stage(1);

    // st9 staging (c = tid) with g folded; batched W9/B9 reductions
    // (overlaps with in-flight bulk copies)
    {
        const int c = tid;
        const float gc = lng[c], bc = lnb[c];
        float wv[9], bv[9];
#pragma unroll
        for (int k = 0; k < 9; k++) {
            int mr = bp + k / 3 - 1, mc = bq + (k % 3) - 1;
            float v = 0.f;
            if ((unsigned)mr < 32u && (unsigned)mc < 32u) {
                size_t idx = ((size_t)((b << 10) + mr * 32 + mc)) * CH + c;
                v = (it == 0) ? g_stok[idx] : g_stacc[it - 1][idx] * Z[36 + k];
            }
            float w = v * gc;
            st9T[c * 12 + k] = w;
            wv[k] = w; bv[k] = v * bc;
        }
#pragma unroll
        for (int k = 0; k < 9; k++) {
            float pw = wv[k], pb = bv[k];
            for (int off = 16; off; off >>= 1) {
                pw += __shfl_down_sync(0xffffffffu, pw, off);
                pb += __shfl_down_sync(0xffffffffu, pb, off);
            }
            if (lane == 0) { atomicAdd(&Z[k], pw); atomicAdd(&Z[9 + k], pb); }
        }
    }
    __syncthreads();   // st9T/W9/B9 visible before pass-1

    const int s = tid >> 6, t = tid & 63;   // 6 s-groups x 8 channels/chunk
    float acc[9];
#pragma unroll
    for (int k = 0; k < 9; k++) acc[k] = 0.f;

#pragma unroll
    for (int j = 0; j < 8; j++) {
        MBAR_WAIT((j & 1) ? mb1 : mb0, (j >> 1) & 1);
        {
            const float* bufp = (j & 1) ? buf1 : buf0;
            const float4* tr4 = (const float4*)(bufp + t * 52 + s * 8);
            const float* wbase = st9T + (j * 48 + s * 8) * 12;
#pragma unroll
            for (int q = 0; q < 2; q++) {
                float4 a4 = tr4[q];
                const float* wr = wbase + q * 48;
                float av[4] = {a4.x, a4.y, a4.z, a4.w};
#pragma unroll
                for (int e = 0; e < 4; e++) {
                    const float* wp = wr + e * 12;
                    float4 w0 = *(const float4*)(wp);
                    float4 w1 = *(const float4*)(wp + 4);
                    float  w8 = wp[8];
                    float a = av[e];
                    acc[0] += a * w0.x; acc[1] += a * w0.y; acc[2] += a * w0.z;
                    acc[3] += a * w0.w; acc[4] += a * w1.x; acc[5] += a * w1.y;
                    acc[6] += a * w1.z; acc[7] += a * w1.w; acc[8] += a * w8;
                }
            }
        }
        __syncthreads();          // all reads of this buffer done
        if (j < 6) stage(j + 2);  // re-arm and refill the freed buffer
    }
#pragma unroll
    for (int k = 0; k < 9; k++) atomicAdd(&L[t * 12 + k], acc[k]);
    __syncthreads();

    // softmax: logit = alpha*A - beta*W9 + B9 ; a' = a * alpha
    if (tid < 64) {
        float2 msv = *(const float2*)(g_musig + (size_t)blk * 128 + tid * 2);
        float lg[9], mx = -1e30f;
#pragma unroll
        for (int k = 0; k < 9; k++) {
            float A = L[tid * 12 + k];
            lg[k] = (msv.y * A - msv.x * Z[k] + Z[9 + k]) * SCALE;
            mx = fmaxf(mx, lg[k]);
        }
        float ssum = 0.f;
#pragma unroll
        for (int k = 0; k < 9; k++) { lg[k] = __expf(lg[k] - mx); ssum += lg[k]; }
        float inv = 1.f / ssum;
#pragma unroll
        for (int k = 0; k < 9; k++) {
            float a = lg[k] * inv;
            L[tid * 12 + k] = a * msv.y;
            float sv = a, tv = msv.x * a;
            for (int off = 16; off; off >>= 1) {
                sv += __shfl_down_sync(0xffffffffu, sv, off);
                tv += __shfl_down_sync(0xffffffffu, tv, off);
            }
            if (lane == 0) {
                atomicAdd(&Z[27 + k], sv);   // S9
                atomicAdd(&Z[18 + k], tv);   // T9
            }
        }
    }
    __syncthreads();

    // pass2: out_ck = g_c*(sum_t raw*a' - T9_k) + b_c*S9_k ; scatter-fold.
    // Channels 288..383 (chunks 6,7) still resident in buf0/buf1.
    {
        float a2[9];
#pragma unroll
        for (int k = 0; k < 9; k++) a2[k] = 0.f;
        if (tid < 288) {
            const float* tp2 = tokbase + tid;
#pragma unroll 4
            for (int t2 = 0; t2 < TPC; t2++) {
                float a = tp2[t2 * CH];
                float4 l0 = *(const float4*)(L + t2 * 12);
                float4 l1 = *(const float4*)(L + t2 * 12 + 4);
                float  l8 = L[t2 * 12 + 8];
                a2[0] += a * l0.x; a2[1] += a * l0.y; a2[2] += a * l0.z;
                a2[3] += a * l0.w; a2[4] += a * l1.x; a2[5] += a * l1.y;
                a2[6] += a * l1.z; a2[7] += a * l1.w; a2[8] += a * l8;
            }
        } else {
            const float* bsm = (tid < 336) ? buf0 : buf1;   // chunk 6 / chunk 7
            const int cl = (tid < 336) ? (tid - 288) : (tid - 336);
#pragma unroll 4
            for (int t2 = 0; t2 < TPC; t2++) {
                float a = bsm[t2 * 52 + cl];
                float4 l0 = *(const float4*)(L + t2 * 12);
                float4 l1 = *(const float4*)(L + t2 * 12 + 4);
                float  l8 = L[t2 * 12 + 8];
                a2[0] += a * l0.x; a2[1] += a * l0.y; a2[2] += a * l0.z;
                a2[3] += a * l0.w; a2[4] += a * l1.x; a2[5] += a * l1.y;
                a2[6] += a * l1.z; a2[7] += a * l1.w; a2[8] += a * l8;
            }
        }
        float gc = lng[tid], bc = lnb[tid];
        float* sa = g_stacc[it];
#pragma unroll
        for (int k = 0; k < 9; k++) {
            int mr = bp + k / 3 - 1, mc = bq + (k % 3) - 1;
            if ((unsigned)mr < 32u && (unsigned)mc < 32u)
                atomicAdd(&sa[((size_t)((b << 10) + mr * 32 + mc)) * CH + tid],
                          gc * (a2[k] - Z[18 + k]) + bc * Z[27 + k]);
        }
    }
    if (tid < 9) {
        int k = tid;
        int mr = bp + k / 3 - 1, mc = bq + (k % 3) - 1;
        if ((unsigned)mr < 32u && (unsigned)mc < 32u)
            atomicAdd(&g_asum[it][(b << 10) + mr * 32 + mc], Z[27 + k]);
    }
}

// ---------------------------------------------------------------------------
// kout: transposed normalize to (B, C, 32, 32) from buffer 3
// ---------------------------------------------------------------------------
__global__ void kout(float* __restrict__ out) {
    __shared__ float tile[32][33];
    __shared__ float as[32];
    const int blk = blockIdx.x;
    const int b = blk / 384;
    const int r = blk % 384;
    const int c0 = (r >> 5) * 32;
    const int cl0 = (r & 31) * 32;
    const int tid = threadIdx.x;
    for (int e = tid; e < 1024; e += 256) {
        int cl = e >> 5, c = e & 31;
        tile[cl][c] = g_stacc[3][((size_t)(b * CELLS + cl0 + cl)) * CH + c0 + c];
    }
    if (tid < 32) as[tid] = g_asum[3][b * CELLS + cl0 + tid] + 1e-12f;
    __syncthreads();
    for (int e = tid; e < 1024; e += 256) {
        int c = e >> 5, cl = e & 31;
        out[((size_t)(b * CH + c0 + c)) * CELLS + cl0 + cl] = tile[cl][c] / as[cl];
    }
}

extern "C" void kernel_launch(void* const* d_in, const int* in_sizes, int n_in,
                              void* d_out, int out_size) {
    const float* x   = (const float*)d_in[0];
    const float* dww = (const float*)d_in[1];
    const float* dwb = (const float*)d_in[2];
    const float* lng = (const float*)d_in[3];
    const float* lnb = (const float*)d_in[4];
    float* out = (float*)d_out;

    const int smemA = (11520 + 3456 + 384 + 1024 + 8) * 4;
    const int smemB = 12080 * 4 + 16;   // buffers + 2 mbarriers
    cudaFuncSetAttribute(p1,  cudaFuncAttributeMaxDynamicSharedMemorySize, smemA);
    cudaFuncSetAttribute(kb5, cudaFuncAttributeMaxDynamicSharedMemorySize, smemB);

    kz<<<(BATCH * CELLS * CH + 255) / 256, 256>>>();       // idx 0
    p1<<<256, 512, smemA>>>(x, dww, dwb, lng, lnb);        // idx 1
    knop<<<1, 32>>>();                                     // idx 2
    for (int it = 0; it < 4; it++)
        kb5<<<BATCH * CELLS, 384, smemB>>>(lng, lnb, it);  // idx 3 -> profile slot 5
    kout<<<768, 256>>>(out);
}

// round 16
// speedup vs baseline: 1.4762x; 1.4762x over previous
#include <cuda_runtime.h>

#define BATCH 2
#define CH 384
#define CELLS 1024
#define TPC 64
#define SCALE 0.05103103630798287f   // 384^-0.5

// Scratch (device globals; allocation forbidden)
__device__ float g_tok  [(size_t)BATCH * CELLS * TPC * CH];   // raw x0, [blk][t][c]
__device__ float g_musig[(size_t)BATCH * CELLS * TPC * 2];    // per-token (beta=mu*rs, alpha=rs)
__device__ float g_stok [(size_t)BATCH * CELLS * CH];         // initial stokens
__device__ float g_stacc[4][(size_t)BATCH * CELLS * CH];      // per-iteration fold accumulators
__device__ float g_asum [4][BATCH * CELLS];

__global__ void knop() {}

__device__ __forceinline__ void cpa16p(unsigned dst, const float* src, int pbytes) {
    asm volatile("cp.async.ca.shared.global [%0], [%1], 16, %2;"
                 :: "r"(dst), "l"(src), "r"(pbytes));
}
__device__ __forceinline__ void cpa4p(unsigned dst, const float* src, int pbytes) {
    asm volatile("cp.async.ca.shared.global [%0], [%1], 4, %2;"
                 :: "r"(dst), "l"(src), "r"(pbytes));
}
__device__ __forceinline__ void cpa_commit() {
    asm volatile("cp.async.commit_group;" ::: "memory");
}

#define MBAR_INIT(mb, cnt) \
    asm volatile("mbarrier.init.shared.b64 [%0], %1;" :: "r"(mb), "r"(cnt) : "memory")
#define MBAR_EXPECT_TX(mb, tx) \
    asm volatile("mbarrier.arrive.expect_tx.shared.b64 _, [%0], %1;" :: "r"(mb), "r"(tx) : "memory")
#define MBAR_WAIT(mb, ph) do {                                              \
    asm volatile("{\n\t.reg .pred P;\n"                                     \
                 "WL%=:\n\t"                                                \
                 "mbarrier.try_wait.parity.acquire.cta.shared::cta.b64 P, [%0], %1, 0x989680;\n\t" \
                 "@P bra WD%=;\n\t"                                         \
                 "bra WL%=;\n"                                              \
                 "WD%=:\n\t}" :: "r"(mb), "r"(ph) : "memory");              \
} while (0)
#define BULK_G2S(dst, src, bytes, mb) \
    asm volatile("cp.async.bulk.shared::cluster.global.mbarrier::complete_tx::bytes [%0], [%1], %2, [%3];" \
                 :: "r"(dst), "l"(src), "r"(bytes), "r"(mb) : "memory")

// ---------------------------------------------------------------------------
// p1: dwconv3x3 + x + bias -> raw x0 tokens + LN stats + initial stokens.
// Block = 8x64 strip, 256 blocks x 512 threads.
// 24 chunks of 16 channels (fat phases: 2x compute per phase vs R7, half the
// barriers, double the prefetch slack). Double-buffered cp.async tiles.
// Tile: [r2(10)][ch(16)][72]; interior cols 4..67, halo at 3 and 68.
// ---------------------------------------------------------------------------
__global__ __launch_bounds__(512, 2) void p1(const float* __restrict__ x,
                                             const float* __restrict__ dww,
                                             const float* __restrict__ dwb,
                                             const float* __restrict__ lng,
                                             const float* __restrict__ lnb) {
    extern __shared__ float sm[];
    float* tiles   = sm;                   // 2 * 11520
    float* wall    = sm + 23040;           // 3456
    float* ball    = wall + 3456;          // 384
    float* musig_s = ball + 384;           // 1024
    float* Scell   = musig_s + 1024;       // 8

    const int tid = threadIdx.x;
    const int blk = blockIdx.x;
    const int b = blk >> 7;
    const int rem = blk & 127;
    const int cellrow = rem >> 2;
    const int qc = rem & 3;
    const int h0 = cellrow * 8, w0 = qc * 64;

    const int px = tid;
    const int p0 = px >> 6, cc0 = px & 63;
    const int cell0 = cc0 >> 3, j0 = cc0 & 7;
    const int t0 = p0 * 8 + j0;
    const size_t cellbase = (size_t)(b * CELLS + cellrow * 32 + qc * 8);
    const size_t gcell0 = cellbase + cell0;
    float* tokrow = g_tok + (gcell0 * TPC + t0) * CH;

    for (int i = tid; i < 3456; i += 512) wall[i] = dww[i];
    if (tid < 384) ball[tid] = dwb[tid];

    const unsigned tA = (unsigned)__cvta_generic_to_shared(tiles);

    auto issue = [&](int j) {
        const int c0 = j * 16;
        const unsigned da = tA + (unsigned)((j & 1) * 11520 * 4);
        for (int i = tid; i < 2560; i += 512) {       // interior, 16B
            int r2 = i >> 8, rr = i & 255, ch = rr >> 4, c4 = rr & 15;
            int gh = h0 - 1 + r2;
            const float* src = x + (((size_t)(b * CH + c0 + ch)) << 16) + (gh << 8) + w0 + c4 * 4;
            cpa16p(da + (unsigned)((r2 * 1152 + ch * 72 + 4 + c4 * 4) * 4), src,
                   ((unsigned)gh < 256u) ? 16 : 0);
        }
        if (tid < 320) {                              // halo cols, 4B
            int r2 = tid >> 5, rr = tid & 31, ch = rr >> 1, side = rr & 1;
            int gh = h0 - 1 + r2;
            int gw = side ? (w0 + 64) : (w0 - 1);
            const float* src = x + (((size_t)(b * CH + c0 + ch)) << 16) + (gh << 8) + gw;
            cpa4p(da + (unsigned)((r2 * 1152 + ch * 72 + (side ? 68 : 3)) * 4), src,
                  ((unsigned)gh < 256u && (unsigned)gw < 256u) ? 4 : 0);
        }
        cpa_commit();
    };

    issue(0);
    issue(1);

    float s0 = 0.f, q0 = 0.f;

    for (int j = 0; j < 24; j++) {
        if (j < 23) asm volatile("cp.async.wait_group 1;" ::: "memory");
        else        asm volatile("cp.async.wait_group 0;" ::: "memory");
        __syncthreads();
        {
            const float* tile = tiles + (j & 1) * 11520;
#pragma unroll
            for (int hf = 0; hf < 2; hf++) {          // two 8-channel halves
                float v[8];
#pragma unroll
                for (int c8 = 0; c8 < 8; c8++) {
                    const int ch = hf * 8 + c8;
                    const float* t0p = tile + p0 * 1152 + ch * 72 + 3 + cc0;
                    float a0 = t0p[0],    a1 = t0p[1],    a2 = t0p[2];
                    float b0 = t0p[1152], b1 = t0p[1153], b2 = t0p[1154];
                    float d0 = t0p[2304], d1 = t0p[2305], d2 = t0p[2306];
                    const float* w = wall + (j * 16 + ch) * 9;
                    float vv = b1 + ball[j * 16 + ch]
                        + a0 * w[0] + a1 * w[1] + a2 * w[2]
                        + b0 * w[3] + b1 * w[4] + b2 * w[5]
                        + d0 * w[6] + d1 * w[7] + d2 * w[8];
                    s0 += vv; q0 += vv * vv;
                    v[c8] = vv;
                }
                *(float4*)(tokrow + j * 16 + hf * 8)     = make_float4(v[0], v[1], v[2], v[3]);
                *(float4*)(tokrow + j * 16 + hf * 8 + 4) = make_float4(v[4], v[5], v[6], v[7]);
            }
        }
        __syncthreads();
        if (j < 22) issue(j + 2);
    }

    // LN stats
    {
        float mu = s0 * (1.f / CH);
        float rs = rsqrtf(q0 * (1.f / CH) - mu * mu + 1e-5f);
        *(float2*)(musig_s + px * 2) = make_float2(mu * rs, rs);
        *(float2*)(g_musig + (gcell0 * TPC + t0) * 2) = make_float2(mu * rs, rs);
    }
    __syncthreads();
    if (tid < 8) {
        float S = 0.f;
        for (int t = 0; t < TPC; t++) {
            int ppx = (t >> 3) * 64 + tid * 8 + (t & 7);
            S += musig_s[ppx * 2];
        }
        Scell[tid] = S;
    }
    __syncthreads();

    // Initial stokens (L2-hot re-read of own tokens)
    for (int u = tid; u < 8 * CH; u += 512) {
        int cell = u / CH, c = u - cell * CH;
        const float* tp = g_tok + (cellbase + cell) * TPC * CH + c;
        float acc = 0.f;
#pragma unroll 8
        for (int t = 0; t < TPC; t++) {
            int ppx = (t >> 3) * 64 + cell * 8 + (t & 7);
            acc += tp[t * CH] * musig_s[ppx * 2 + 1];
        }
        g_stok[(cellbase + cell) * CH + c] =
            lng[c] * (acc - Scell[cell]) * (1.f / 64.f) + lnb[c];
    }
}

// ---------------------------------------------------------------------------
// kz: zero all accumulator buffers
// ---------------------------------------------------------------------------
__global__ void kz() {
    int i = blockIdx.x * 256 + threadIdx.x;
    if (i < BATCH * CELLS * CH) {
#pragma unroll
        for (int r = 0; r < 4; r++) g_stacc[r][i] = 0.f;
        if (i < BATCH * CELLS) {
#pragma unroll
            for (int r = 0; r < 4; r++) g_asum[r][i] = 0.f;
        }
    }
}

// ---------------------------------------------------------------------------
// kb4 (R14-exact, measured best 124us/iter): bulk staging + mbarriers,
// 4 chunks of 96 channels, occupancy 3.
// Z: [0..8]=W9, [9..17]=B9, [18..26]=T9, [27..35]=S9, [36..44]=recip(asum)
// ---------------------------------------------------------------------------
__global__ __launch_bounds__(384, 3) void kb4(const float* __restrict__ lng,
                                              const float* __restrict__ lnb,
                                              int it) {
    extern __shared__ float sm[];
    float* buf0 = sm;                 // 64*100 = 6400
    float* buf1 = sm + 6400;          // 6400
    float* st9T = sm + 12800;         // 4608
    float* L    = st9T + 4608;        // 768
    float* Z    = L + 768;            // 48
    // mbarriers at float index 18224 (byte 72896, 8B aligned)

    const int tid  = threadIdx.x;
    const int lane = tid & 31;
    const int blk  = blockIdx.x;
    const int b    = blk >> 10;
    const int cell = blk & 1023;
    const int bp = cell >> 5, bq = cell & 31;
    const float* tokbase = g_tok + (size_t)blk * TPC * CH;

    const unsigned smb = (unsigned)__cvta_generic_to_shared(sm);
    const unsigned b0a = smb;
    const unsigned b1a = smb + 6400u * 4u;
    const unsigned mb0 = smb + 18224u * 4u;
    const unsigned mb1 = mb0 + 8u;

    for (int i = tid; i < 768; i += 384) L[i] = 0.f;
    if (tid < 36) Z[tid] = 0.f;
    if (tid >= 36 && tid < 45) {
        int k = tid - 36;
        int mr = bp + k / 3 - 1, mc = bq + (k % 3) - 1;
        float r = 1.f;
        if (it > 0 && (unsigned)mr < 32u && (unsigned)mc < 32u)
            r = __fdividef(1.f, g_asum[it - 1][(b << 10) + mr * 32 + mc] + 1e-12f);
        Z[tid] = r;
    }
    if (tid == 0) { MBAR_INIT(mb0, 1); MBAR_INIT(mb1, 1); }
    __syncthreads();

    // stage chunk via 64 bulk row-copies (384B each)
    auto stage = [&](int chunk) {
        const unsigned mb = (chunk & 1) ? mb1 : mb0;
        const unsigned da = (chunk & 1) ? b1a : b0a;
        if (tid == 0) MBAR_EXPECT_TX(mb, 24576u);
        if (tid < 64)
            BULK_G2S(da + (unsigned)tid * 400u,
                     tokbase + tid * CH + chunk * 96, 384u, mb);
    };

    stage(0);
    stage(1);

    // st9 staging (c = tid) with g folded; batched W9/B9 reductions
    // (overlaps with in-flight bulk copies)
    {
        const int c = tid;
        const float gc = lng[c], bc = lnb[c];
        float wv[9], bv[9];
#pragma unroll
        for (int k = 0; k < 9; k++) {
            int mr = bp + k / 3 - 1, mc = bq + (k % 3) - 1;
            float v = 0.f;
            if ((unsigned)mr < 32u && (unsigned)mc < 32u) {
                size_t idx = ((size_t)((b << 10) + mr * 32 + mc)) * CH + c;
                v = (it == 0) ? g_stok[idx] : g_stacc[it - 1][idx] * Z[36 + k];
            }
            float w = v * gc;
            st9T[c * 12 + k] = w;
            wv[k] = w; bv[k] = v * bc;
        }
#pragma unroll
        for (int k = 0; k < 9; k++) {
            float pw = wv[k], pb = bv[k];
            for (int off = 16; off; off >>= 1) {
                pw += __shfl_down_sync(0xffffffffu, pw, off);
                pb += __shfl_down_sync(0xffffffffu, pb, off);
            }
            if (lane == 0) { atomicAdd(&Z[k], pw); atomicAdd(&Z[9 + k], pb); }
        }
    }
    __syncthreads();   // st9T/W9/B9 visible to all before pass-1

    const int s = tid >> 6, t = tid & 63;
    float acc[9];
#pragma unroll
    for (int k = 0; k < 9; k++) acc[k] = 0.f;

#pragma unroll
    for (int j = 0; j < 4; j++) {
        MBAR_WAIT((j & 1) ? mb1 : mb0, j >> 1);
        {
            const float* bufp = (j & 1) ? buf1 : buf0;
            const float4* tr4 = (const float4*)(bufp + t * 100 + s * 16);
            const float* wbase = st9T + (j * 96 + s * 16) * 12;
#pragma unroll
            for (int q = 0; q < 4; q++) {
                float4 a4 = tr4[q];
                const float* wr = wbase + q * 48;
                float av[4] = {a4.x, a4.y, a4.z, a4.w};
#pragma unroll
                for (int e = 0; e < 4; e++) {
                    const float* wp = wr + e * 12;
                    float4 w0 = *(const float4*)(wp);
                    float4 w1 = *(const float4*)(wp + 4);
                    float  w8 = wp[8];
                    float a = av[e];
                    acc[0] += a * w0.x; acc[1] += a * w0.y; acc[2] += a * w0.z;
                    acc[3] += a * w0.w; acc[4] += a * w1.x; acc[5] += a * w1.y;
                    acc[6] += a * w1.z; acc[7] += a * w1.w; acc[8] += a * w8;
                }
            }
        }
        __syncthreads();          // all reads of this buffer done
        if (j < 2) stage(j + 2);  // re-arm and refill the freed buffer
    }
#pragma unroll
    for (int k = 0; k < 9; k++) atomicAdd(&L[t * 12 + k], acc[k]);
    __syncthreads();

    // softmax: logit = alpha*A - beta*W9 + B9 ; a' = a * alpha
    if (tid < 64) {
        float2 msv = *(const float2*)(g_musig + (size_t)blk * 128 + tid * 2);
        float lg[9], mx = -1e30f;
#pragma unroll
        for (int k = 0; k < 9; k++) {
            float A = L[tid * 12 + k];
            lg[k] = (msv.y * A - msv.x * Z[k] + Z[9 + k]) * SCALE;
            mx = fmaxf(mx, lg[k]);
        }
        float ssum = 0.f;
#pragma unroll
        for (int k = 0; k < 9; k++) { lg[k] = __expf(lg[k] - mx); ssum += lg[k]; }
        float inv = 1.f / ssum;
#pragma unroll
        for (int k = 0; k < 9; k++) {
            float a = lg[k] * inv;
            L[tid * 12 + k] = a * msv.y;
            float sv = a, tv = msv.x * a;
            for (int off = 16; off; off >>= 1) {
                sv += __shfl_down_sync(0xffffffffu, sv, off);
                tv += __shfl_down_sync(0xffffffffu, tv, off);
            }
            if (lane == 0) {
                atomicAdd(&Z[27 + k], sv);   // S9
                atomicAdd(&Z[18 + k], tv);   // T9
            }
        }
    }
    __syncthreads();

    // pass2: out_ck = g_c*(sum_t raw*a' - T9_k) + b_c*S9_k ; scatter-fold.
    // Channels 192..383 (chunks 2,3) still resident in buf0/buf1.
    {
        float a2[9];
#pragma unroll
        for (int k = 0; k < 9; k++) a2[k] = 0.f;
        if (tid < 192) {
            const float* tp2 = tokbase + tid;
#pragma unroll 4
            for (int t2 = 0; t2 < TPC; t2++) {
                float a = tp2[t2 * CH];
                float4 l0 = *(const float4*)(L + t2 * 12);
                float4 l1 = *(const float4*)(L + t2 * 12 + 4);
                float  l8 = L[t2 * 12 + 8];
                a2[0] += a * l0.x; a2[1] += a * l0.y; a2[2] += a * l0.z;
                a2[3] += a * l0.w; a2[4] += a * l1.x; a2[5] += a * l1.y;
                a2[6] += a * l1.z; a2[7] += a * l1.w; a2[8] += a * l8;
            }
        } else {
            const float* bsm = (tid < 288) ? buf0 : buf1;
            const int cl = (tid < 288) ? (tid - 192) : (tid - 288);
#pragma unroll 4
            for (int t2 = 0; t2 < TPC; t2++) {
                float a = bsm[t2 * 100 + cl];
                float4 l0 = *(const float4*)(L + t2 * 12);
                float4 l1 = *(const float4*)(L + t2 * 12 + 4);
                float  l8 = L[t2 * 12 + 8];
                a2[0] += a * l0.x; a2[1] += a * l0.y; a2[2] += a * l0.z;
                a2[3] += a * l0.w; a2[4] += a * l1.x; a2[5] += a * l1.y;
                a2[6] += a * l1.z; a2[7] += a * l1.w; a2[8] += a * l8;
            }
        }
        float gc = lng[tid], bc = lnb[tid];
        float* sa = g_stacc[it];
#pragma unroll
        for (int k = 0; k < 9; k++) {
            int mr = bp + k / 3 - 1, mc = bq + (k % 3) - 1;
            if ((unsigned)mr < 32u && (unsigned)mc < 32u)
                atomicAdd(&sa[((size_t)((b << 10) + mr * 32 + mc)) * CH + tid],
                          gc * (a2[k] - Z[18 + k]) + bc * Z[27 + k]);
        }
    }
    if (tid < 9) {
        int k = tid;
        int mr = bp + k / 3 - 1, mc = bq + (k % 3) - 1;
        if ((unsigned)mr < 32u && (unsigned)mc < 32u)
            atomicAdd(&g_asum[it][(b << 10) + mr * 32 + mc], Z[27 + k]);
    }
}

// ---------------------------------------------------------------------------
// kout: transposed normalize to (B, C, 32, 32) from buffer 3
// ---------------------------------------------------------------------------
__global__ void kout(float* __restrict__ out) {
    __shared__ float tile[32][33];
    __shared__ float as[32];
    const int blk = blockIdx.x;
    const int b = blk / 384;
    const int r = blk % 384;
    const int c0 = (r >> 5) * 32;
    const int cl0 = (r & 31) * 32;
    const int tid = threadIdx.x;
    for (int e = tid; e < 1024; e += 256) {
        int cl = e >> 5, c = e & 31;
        tile[cl][c] = g_stacc[3][((size_t)(b * CELLS + cl0 + cl)) * CH + c0 + c];
    }
    if (tid < 32) as[tid] = g_asum[3][b * CELLS + cl0 + tid] + 1e-12f;
    __syncthreads();
    for (int e = tid; e < 1024; e += 256) {
        int c = e >> 5, cl = e & 31;
        out[((size_t)(b * CH + c0 + c)) * CELLS + cl0 + cl] = tile[cl][c] / as[cl];
    }
}

extern "C" void kernel_launch(void* const* d_in, const int* in_sizes, int n_in,
                              void* d_out, int out_size) {
    const float* x   = (const float*)d_in[0];
    const float* dww = (const float*)d_in[1];
    const float* dwb = (const float*)d_in[2];
    const float* lng = (const float*)d_in[3];
    const float* lnb = (const float*)d_in[4];
    float* out = (float*)d_out;

    const int smemA = (23040 + 3456 + 384 + 1024 + 8) * 4;   // 111.6 KB
    const int smemB = 18224 * 4 + 16;   // buffers + 2 mbarriers
    cudaFuncSetAttribute(p1,  cudaFuncAttributeMaxDynamicSharedMemorySize, smemA);
    cudaFuncSetAttribute(kb4, cudaFuncAttributeMaxDynamicSharedMemorySize, smemB);

    kz<<<(BATCH * CELLS * CH + 255) / 256, 256>>>();       // idx 0
    knop<<<1, 32>>>();                                     // idx 1
    knop<<<1, 32>>>();                                     // idx 2
    p1<<<256, 512, smemA>>>(x, dww, dwb, lng, lnb);        // idx 3 -> profile slot 5
    for (int it = 0; it < 4; it++)
        kb4<<<BATCH * CELLS, 384, smemB>>>(lng, lnb, it);
    kout<<<768, 256>>>(out);
}

// round 17
// speedup vs baseline: 1.5788x; 1.0695x over previous
#include <cuda_runtime.h>

#define BATCH 2
#define CH 384
#define CELLS 1024
#define TPC 64
#define SCALE 0.05103103630798287f   // 384^-0.5

// Scratch (device globals; allocation forbidden)
__device__ float g_tok  [(size_t)BATCH * CELLS * TPC * CH];   // raw x0, [blk][t][c]
__device__ float g_musig[(size_t)BATCH * CELLS * TPC * 2];    // per-token (beta=mu*rs, alpha=rs)
__device__ float g_stok [(size_t)BATCH * CELLS * CH];         // initial stokens
__device__ float g_stacc[4][(size_t)BATCH * CELLS * CH];      // per-iteration fold accumulators
__device__ float g_asum [4][BATCH * CELLS];

__global__ void knop() {}

__device__ __forceinline__ void cpa16p(unsigned dst, const float* src, int pbytes) {
    asm volatile("cp.async.ca.shared.global [%0], [%1], 16, %2;"
                 :: "r"(dst), "l"(src), "r"(pbytes));
}
__device__ __forceinline__ void cpa4p(unsigned dst, const float* src, int pbytes) {
    asm volatile("cp.async.ca.shared.global [%0], [%1], 4, %2;"
                 :: "r"(dst), "l"(src), "r"(pbytes));
}
__device__ __forceinline__ void cpa_commit() {
    asm volatile("cp.async.commit_group;" ::: "memory");
}

#define MBAR_INIT(mb, cnt) \
    asm volatile("mbarrier.init.shared.b64 [%0], %1;" :: "r"(mb), "r"(cnt) : "memory")
#define MBAR_EXPECT_TX(mb, tx) \
    asm volatile("mbarrier.arrive.expect_tx.shared.b64 _, [%0], %1;" :: "r"(mb), "r"(tx) : "memory")
#define MBAR_WAIT(mb, ph) do {                                              \
    asm volatile("{\n\t.reg .pred P;\n"                                     \
                 "WL%=:\n\t"                                                \
                 "mbarrier.try_wait.parity.acquire.cta.shared::cta.b64 P, [%0], %1, 0x989680;\n\t" \
                 "@P bra WD%=;\n\t"                                         \
                 "bra WL%=;\n"                                              \
                 "WD%=:\n\t}" :: "r"(mb), "r"(ph) : "memory");              \
} while (0)
#define BULK_G2S(dst, src, bytes, mb) \
    asm volatile("cp.async.bulk.shared::cluster.global.mbarrier::complete_tx::bytes [%0], [%1], %2, [%3];" \
                 :: "r"(dst), "l"(src), "r"(bytes), "r"(mb) : "memory")

// Packed fp32x2 FMA (FFMA2 — only reachable via PTX)
__device__ __forceinline__ void fma2(unsigned long long& acc,
                                     unsigned long long a, unsigned long long b) {
    asm("fma.rn.f32x2 %0, %1, %2, %0;" : "+l"(acc) : "l"(a), "l"(b));
}
__device__ __forceinline__ unsigned long long pack2(float a) {
    unsigned long long r;
    asm("mov.b64 %0, {%1, %1};" : "=l"(r) : "f"(a));
    return r;
}
__device__ __forceinline__ void unpack2(unsigned long long v, float& lo, float& hi) {
    asm("mov.b64 {%0, %1}, %2;" : "=f"(lo), "=f"(hi) : "l"(v));
}
__device__ __forceinline__ void lds_2u64(unsigned addr,
                                         unsigned long long& a, unsigned long long& b) {
    asm("ld.shared.v2.u64 {%0, %1}, [%2];" : "=l"(a), "=l"(b) : "r"(addr));
}
__device__ __forceinline__ float lds_f32(unsigned addr) {
    float v;
    asm("ld.shared.f32 %0, [%1];" : "=f"(v) : "r"(addr));
    return v;
}

// ---------------------------------------------------------------------------
// p1 (R7-exact, measured best 221us): dwconv3x3 + x + bias -> raw x0 tokens +
// LN stats + initial stokens. Block = 8x64 strip, 256 blocks x 512 threads.
// ---------------------------------------------------------------------------
__global__ __launch_bounds__(512, 2) void p1(const float* __restrict__ x,
                                             const float* __restrict__ dww,
                                             const float* __restrict__ dwb,
                                             const float* __restrict__ lng,
                                             const float* __restrict__ lnb) {
    extern __shared__ float sm[];
    float* tiles   = sm;                   // 2 * 5760
    float* wall    = sm + 11520;           // 3456
    float* ball    = wall + 3456;          // 384
    float* musig_s = ball + 384;           // 1024
    float* Scell   = musig_s + 1024;       // 8

    const int tid = threadIdx.x;
    const int blk = blockIdx.x;
    const int b = blk >> 7;
    const int rem = blk & 127;
    const int cellrow = rem >> 2;
    const int qc = rem & 3;
    const int h0 = cellrow * 8, w0 = qc * 64;

    const int px = tid;
    const int p0 = px >> 6, cc0 = px & 63;
    const int cell0 = cc0 >> 3, j0 = cc0 & 7;
    const int t0 = p0 * 8 + j0;
    const size_t cellbase = (size_t)(b * CELLS + cellrow * 32 + qc * 8);
    const size_t gcell0 = cellbase + cell0;
    float* tokrow = g_tok + (gcell0 * TPC + t0) * CH;

    for (int i = tid; i < 3456; i += 512) wall[i] = dww[i];
    if (tid < 384) ball[tid] = dwb[tid];

    const unsigned tA = (unsigned)__cvta_generic_to_shared(tiles);

    auto issue = [&](int j) {
        const int c0 = j * 8;
        const unsigned da = tA + (unsigned)((j & 1) * 5760 * 4);
        for (int i = tid; i < 1280; i += 512) {       // interior, 16B
            int r2 = i >> 7, rr = i & 127, ch = rr >> 4, c4 = rr & 15;
            int gh = h0 - 1 + r2;
            const float* src = x + (((size_t)(b * CH + c0 + ch)) << 16) + (gh << 8) + w0 + c4 * 4;
            cpa16p(da + (unsigned)((r2 * 576 + ch * 72 + 4 + c4 * 4) * 4), src,
                   ((unsigned)gh < 256u) ? 16 : 0);
        }
        for (int i = tid; i < 160; i += 512) {        // halo cols, 4B
            int r2 = i / 16, rr = i & 15, ch = rr >> 1, side = rr & 1;
            int gh = h0 - 1 + r2;
            int gw = side ? (w0 + 64) : (w0 - 1);
            const float* src = x + (((size_t)(b * CH + c0 + ch)) << 16) + (gh << 8) + gw;
            cpa4p(da + (unsigned)((r2 * 576 + ch * 72 + (side ? 68 : 3)) * 4), src,
                  ((unsigned)gh < 256u && (unsigned)gw < 256u) ? 4 : 0);
        }
        cpa_commit();
    };

    issue(0);
    issue(1);

    float s0 = 0.f, q0 = 0.f;

    for (int j = 0; j < 48; j++) {
        if (j < 47) asm volatile("cp.async.wait_group 1;" ::: "memory");
        else        asm volatile("cp.async.wait_group 0;" ::: "memory");
        __syncthreads();
        {
            const float* tile = tiles + (j & 1) * 5760;
            float v[8];
#pragma unroll
            for (int ch = 0; ch < 8; ch++) {
                const float* t0p = tile + p0 * 576 + ch * 72 + 3 + cc0;
                float a0 = t0p[0],    a1 = t0p[1],    a2 = t0p[2];
                float b0 = t0p[576],  b1 = t0p[577],  b2 = t0p[578];
                float d0 = t0p[1152], d1 = t0p[1153], d2 = t0p[1154];
                const float* w = wall + (j * 8 + ch) * 9;
                float vv = b1 + ball[j * 8 + ch]
                    + a0 * w[0] + a1 * w[1] + a2 * w[2]
                    + b0 * w[3] + b1 * w[4] + b2 * w[5]
                    + d0 * w[6] + d1 * w[7] + d2 * w[8];
                s0 += vv; q0 += vv * vv;
                v[ch] = vv;
            }
            *(float4*)(tokrow + j * 8)     = make_float4(v[0], v[1], v[2], v[3]);
            *(float4*)(tokrow + j * 8 + 4) = make_float4(v[4], v[5], v[6], v[7]);
        }
        __syncthreads();
        if (j < 46) issue(j + 2);
    }

    // LN stats
    {
        float mu = s0 * (1.f / CH);
        float rs = rsqrtf(q0 * (1.f / CH) - mu * mu + 1e-5f);
        *(float2*)(musig_s + px * 2) = make_float2(mu * rs, rs);
        *(float2*)(g_musig + (gcell0 * TPC + t0) * 2) = make_float2(mu * rs, rs);
    }
    __syncthreads();
    if (tid < 8) {
        float S = 0.f;
        for (int t = 0; t < TPC; t++) {
            int ppx = (t >> 3) * 64 + tid * 8 + (t & 7);
            S += musig_s[ppx * 2];
        }
        Scell[tid] = S;
    }
    __syncthreads();

    // Initial stokens (L2-hot re-read of own tokens)
    for (int u = tid; u < 8 * CH; u += 512) {
        int cell = u / CH, c = u - cell * CH;
        const float* tp = g_tok + (cellbase + cell) * TPC * CH + c;
        float acc = 0.f;
#pragma unroll 8
        for (int t = 0; t < TPC; t++) {
            int ppx = (t >> 3) * 64 + cell * 8 + (t & 7);
            acc += tp[t * CH] * musig_s[ppx * 2 + 1];
        }
        g_stok[(cellbase + cell) * CH + c] =
            lng[c] * (acc - Scell[cell]) * (1.f / 64.f) + lnb[c];
    }
}

// ---------------------------------------------------------------------------
// kz: zero all accumulator buffers
// ---------------------------------------------------------------------------
__global__ void kz() {
    int i = blockIdx.x * 256 + threadIdx.x;
    if (i < BATCH * CELLS * CH) {
#pragma unroll
        for (int r = 0; r < 4; r++) g_stacc[r][i] = 0.f;
        if (i < BATCH * CELLS) {
#pragma unroll
            for (int r = 0; r < 4; r++) g_asum[r][i] = 0.f;
        }
    }
}

// ---------------------------------------------------------------------------
// kb6: kb4 (bulk staging + mbarriers, 4x96ch chunks, occ 3) with FFMA2
// packed inner loops: fma.rn.f32x2 on (k0,k1)(k2,k3)(k4,k5)(k6,k7) + scalar k8.
// st9T/L rows are 48B, 16B-aligned -> direct ld.shared.v2.u64, no repacking.
// Z: [0..8]=W9, [9..17]=B9, [18..26]=T9, [27..35]=S9, [36..44]=recip(asum)
// ---------------------------------------------------------------------------
__global__ __launch_bounds__(384, 3) void kb6(const float* __restrict__ lng,
                                              const float* __restrict__ lnb,
                                              int it) {
    extern __shared__ float sm[];
    float* buf0 = sm;                 // 64*100 = 6400
    float* buf1 = sm + 6400;          // 6400
    float* st9T = sm + 12800;         // 4608 (pitch 12, rows 48B @16B align)
    float* L    = st9T + 4608;        // 768  (pitch 12)
    float* Z    = L + 768;            // 48
    // mbarriers at float index 18224

    const int tid  = threadIdx.x;
    const int lane = tid & 31;
    const int blk  = blockIdx.x;
    const int b    = blk >> 10;
    const int cell = blk & 1023;
    const int bp = cell >> 5, bq = cell & 31;
    const float* tokbase = g_tok + (size_t)blk * TPC * CH;

    const unsigned smb = (unsigned)__cvta_generic_to_shared(sm);
    const unsigned b0a = smb;
    const unsigned b1a = smb + 6400u * 4u;
    const unsigned st9a = smb + 12800u * 4u;
    const unsigned La   = smb + 17408u * 4u;
    const unsigned mb0 = smb + 18224u * 4u;
    const unsigned mb1 = mb0 + 8u;

    for (int i = tid; i < 768; i += 384) L[i] = 0.f;
    if (tid < 36) Z[tid] = 0.f;
    if (tid >= 36 && tid < 45) {
        int k = tid - 36;
        int mr = bp + k / 3 - 1, mc = bq + (k % 3) - 1;
        float r = 1.f;
        if (it > 0 && (unsigned)mr < 32u && (unsigned)mc < 32u)
            r = __fdividef(1.f, g_asum[it - 1][(b << 10) + mr * 32 + mc] + 1e-12f);
        Z[tid] = r;
    }
    if (tid == 0) { MBAR_INIT(mb0, 1); MBAR_INIT(mb1, 1); }
    __syncthreads();

    // stage chunk via 64 bulk row-copies (384B each)
    auto stage = [&](int chunk) {
        const unsigned mb = (chunk & 1) ? mb1 : mb0;
        const unsigned da = (chunk & 1) ? b1a : b0a;
        if (tid == 0) MBAR_EXPECT_TX(mb, 24576u);
        if (tid < 64)
            BULK_G2S(da + (unsigned)tid * 400u,
                     tokbase + tid * CH + chunk * 96, 384u, mb);
    };

    stage(0);
    stage(1);

    // st9 staging (c = tid) with g folded; batched W9/B9 reductions
    {
        const int c = tid;
        const float gc = lng[c], bc = lnb[c];
        float wv[9], bv[9];
#pragma unroll
        for (int k = 0; k < 9; k++) {
            int mr = bp + k / 3 - 1, mc = bq + (k % 3) - 1;
            float v = 0.f;
            if ((unsigned)mr < 32u && (unsigned)mc < 32u) {
                size_t idx = ((size_t)((b << 10) + mr * 32 + mc)) * CH + c;
                v = (it == 0) ? g_stok[idx] : g_stacc[it - 1][idx] * Z[36 + k];
            }
            float w = v * gc;
            st9T[c * 12 + k] = w;
            wv[k] = w; bv[k] = v * bc;
        }
#pragma unroll
        for (int k = 0; k < 9; k++) {
            float pw = wv[k], pb = bv[k];
            for (int off = 16; off; off >>= 1) {
                pw += __shfl_down_sync(0xffffffffu, pw, off);
                pb += __shfl_down_sync(0xffffffffu, pb, off);
            }
            if (lane == 0) { atomicAdd(&Z[k], pw); atomicAdd(&Z[9 + k], pb); }
        }
    }
    __syncthreads();   // st9T/W9/B9 visible before pass-1

    const int s = tid >> 6, t = tid & 63;
    unsigned long long a01 = 0ull, a23 = 0ull, a45 = 0ull, a67 = 0ull;
    float a8 = 0.f;

#pragma unroll
    for (int j = 0; j < 4; j++) {
        MBAR_WAIT((j & 1) ? mb1 : mb0, j >> 1);
        {
            const float* bufp = (j & 1) ? buf1 : buf0;
            const float4* tr4 = (const float4*)(bufp + t * 100 + s * 16);
            const unsigned wbase = st9a + (unsigned)((j * 96 + s * 16) * 48);
#pragma unroll
            for (int q = 0; q < 4; q++) {
                float4 a4 = tr4[q];
                const unsigned wq = wbase + (unsigned)(q * 192);
                float av[4] = {a4.x, a4.y, a4.z, a4.w};
#pragma unroll
                for (int e = 0; e < 4; e++) {
                    const unsigned wa = wq + (unsigned)(e * 48);
                    unsigned long long w01, w23, w45, w67;
                    lds_2u64(wa, w01, w23);
                    lds_2u64(wa + 16u, w45, w67);
                    float w8 = lds_f32(wa + 32u);
                    unsigned long long aa = pack2(av[e]);
                    fma2(a01, aa, w01);
                    fma2(a23, aa, w23);
                    fma2(a45, aa, w45);
                    fma2(a67, aa, w67);
                    a8 += av[e] * w8;
                }
            }
        }
        __syncthreads();          // all reads of this buffer done
        if (j < 2) stage(j + 2);  // re-arm and refill the freed buffer
    }
    {
        float r0, r1;
        unpack2(a01, r0, r1); atomicAdd(&L[t * 12 + 0], r0); atomicAdd(&L[t * 12 + 1], r1);
        unpack2(a23, r0, r1); atomicAdd(&L[t * 12 + 2], r0); atomicAdd(&L[t * 12 + 3], r1);
        unpack2(a45, r0, r1); atomicAdd(&L[t * 12 + 4], r0); atomicAdd(&L[t * 12 + 5], r1);
        unpack2(a67, r0, r1); atomicAdd(&L[t * 12 + 6], r0); atomicAdd(&L[t * 12 + 7], r1);
        atomicAdd(&L[t * 12 + 8], a8);
    }
    __syncthreads();

    // softmax: logit = alpha*A - beta*W9 + B9 ; a' = a * alpha
    if (tid < 64) {
        float2 msv = *(const float2*)(g_musig + (size_t)blk * 128 + tid * 2);
        float lg[9], mx = -1e30f;
#pragma unroll
        for (int k = 0; k < 9; k++) {
            float A = L[tid * 12 + k];
            lg[k] = (msv.y * A - msv.x * Z[k] + Z[9 + k]) * SCALE;
            mx = fmaxf(mx, lg[k]);
        }
        float ssum = 0.f;
#pragma unroll
        for (int k = 0; k < 9; k++) { lg[k] = __expf(lg[k] - mx); ssum += lg[k]; }
        float inv = 1.f / ssum;
#pragma unroll
        for (int k = 0; k < 9; k++) {
            float a = lg[k] * inv;
            L[tid * 12 + k] = a * msv.y;
            float sv = a, tv = msv.x * a;
            for (int off = 16; off; off >>= 1) {
                sv += __shfl_down_sync(0xffffffffu, sv, off);
                tv += __shfl_down_sync(0xffffffffu, tv, off);
            }
            if (lane == 0) {
                atomicAdd(&Z[27 + k], sv);   // S9
                atomicAdd(&Z[18 + k], tv);   // T9
            }
        }
    }
    __syncthreads();

    // pass2 (FFMA2): out_ck = g_c*(sum_t raw*a' - T9_k) + b_c*S9_k.
    // Channels 192..383 (chunks 2,3) still resident in buf0/buf1.
    {
        unsigned long long x01 = 0ull, x23 = 0ull, x45 = 0ull, x67 = 0ull;
        float x8 = 0.f;
        if (tid < 192) {
            const float* tp2 = tokbase + tid;
#pragma unroll 4
            for (int t2 = 0; t2 < TPC; t2++) {
                float a = tp2[t2 * CH];
                const unsigned la = La + (unsigned)(t2 * 48);
                unsigned long long l01, l23, l45, l67;
                lds_2u64(la, l01, l23);
                lds_2u64(la + 16u, l45, l67);
                float l8 = lds_f32(la + 32u);
                unsigned long long aa = pack2(a);
                fma2(x01, aa, l01);
                fma2(x23, aa, l23);
                fma2(x45, aa, l45);
                fma2(x67, aa, l67);
                x8 += a * l8;
            }
        } else {
            const float* bsm = (tid < 288) ? buf0 : buf1;
            const int cl = (tid < 288) ? (tid - 192) : (tid - 288);
#pragma unroll 4
            for (int t2 = 0; t2 < TPC; t2++) {
                float a = bsm[t2 * 100 + cl];
                const unsigned la = La + (unsigned)(t2 * 48);
                unsigned long long l01, l23, l45, l67;
                lds_2u64(la, l01, l23);
                lds_2u64(la + 16u, l45, l67);
                float l8 = lds_f32(la + 32u);
                unsigned long long aa = pack2(a);
                fma2(x01, aa, l01);
                fma2(x23, aa, l23);
                fma2(x45, aa, l45);
                fma2(x67, aa, l67);
                x8 += a * l8;
            }
        }
        float a2[9];
        unpack2(x01, a2[0], a2[1]);
        unpack2(x23, a2[2], a2[3]);
        unpack2(x45, a2[4], a2[5]);
        unpack2(x67, a2[6], a2[7]);
        a2[8] = x8;
        float gc = lng[tid], bc = lnb[tid];
        float* sa = g_stacc[it];
#pragma unroll
        for (int k = 0; k < 9; k++) {
            int mr = bp + k / 3 - 1, mc = bq + (k % 3) - 1;
            if ((unsigned)mr < 32u && (unsigned)mc < 32u)
                atomicAdd(&sa[((size_t)((b << 10) + mr * 32 + mc)) * CH + tid],
                          gc * (a2[k] - Z[18 + k]) + bc * Z[27 + k]);
        }
    }
    if (tid < 9) {
        int k = tid;
        int mr = bp + k / 3 - 1, mc = bq + (k % 3) - 1;
        if ((unsigned)mr < 32u && (unsigned)mc < 32u)
            atomicAdd(&g_asum[it][(b << 10) + mr * 32 + mc], Z[27 + k]);
    }
}

// ---------------------------------------------------------------------------
// kout: transposed normalize to (B, C, 32, 32) from buffer 3
// ---------------------------------------------------------------------------
__global__ void kout(float* __restrict__ out) {
    __shared__ float tile[32][33];
    __shared__ float as[32];
    const int blk = blockIdx.x;
    const int b = blk / 384;
    const int r = blk % 384;
    const int c0 = (r >> 5) * 32;
    const int cl0 = (r & 31) * 32;
    const int tid = threadIdx.x;
    for (int e = tid; e < 1024; e += 256) {
        int cl = e >> 5, c = e & 31;
        tile[cl][c] = g_stacc[3][((size_t)(b * CELLS + cl0 + cl)) * CH + c0 + c];
    }
    if (tid < 32) as[tid] = g_asum[3][b * CELLS + cl0 + tid] + 1e-12f;
    __syncthreads();
    for (int e = tid; e < 1024; e += 256) {
        int c = e >> 5, cl = e & 31;
        out[((size_t)(b * CH + c0 + c)) * CELLS + cl0 + cl] = tile[cl][c] / as[cl];
    }
}

extern "C" void kernel_launch(void* const* d_in, const int* in_sizes, int n_in,
                              void* d_out, int out_size) {
    const float* x   = (const float*)d_in[0];
    const float* dww = (const float*)d_in[1];
    const float* dwb = (const float*)d_in[2];
    const float* lng = (const float*)d_in[3];
    const float* lnb = (const float*)d_in[4];
    float* out = (float*)d_out;

    const int smemA = (11520 + 3456 + 384 + 1024 + 8) * 4;
    const int smemB = 18224 * 4 + 16;   // buffers + 2 mbarriers
    cudaFuncSetAttribute(p1,  cudaFuncAttributeMaxDynamicSharedMemorySize, smemA);
    cudaFuncSetAttribute(kb6, cudaFuncAttributeMaxDynamicSharedMemorySize, smemB);

    kz<<<(BATCH * CELLS * CH + 255) / 256, 256>>>();       // idx 0
    p1<<<256, 512, smemA>>>(x, dww, dwb, lng, lnb);        // idx 1
    knop<<<1, 32>>>();                                     // idx 2
    for (int it = 0; it < 4; it++)
        kb6<<<BATCH * CELLS, 384, smemB>>>(lng, lnb, it);  // idx 3 -> profile slot 5
    kout<<<768, 256>>>(out);
}